// round 1
// baseline (speedup 1.0000x reference)
#include <cuda_runtime.h>
#include <cuda_bf16.h>
#include <cstddef>

// Problem constants (match reference_code)
#define T_STEPS 600
#define N_REC   5000
#define N_IN    100
#define N_OUT   100
// N_REC in float4 units
#define NR4     1250   // 5000/4

// Scratch (allocation-free rule: __device__ globals)
__device__ float g_x[N_REC];                       // recurrent pre-activation state
__device__ float g_drive[(size_t)T_STEPS * N_REC]; // u @ W_in^T + eps, precomputed

// ---------------------------------------------------------------------------
// init: hidden[0] = r, x = arctanh(r)
// ---------------------------------------------------------------------------
__global__ void init_kernel(const float* __restrict__ r, float* __restrict__ hidden) {
    int i = blockIdx.x * blockDim.x + threadIdx.x;
    if (i < N_REC) {
        float rv = r[i];
        hidden[i] = rv;
        g_x[i] = atanhf(rv);
    }
}

// ---------------------------------------------------------------------------
// drive[t][i] = sum_k u[t][k] * W_in[i][k] + eps[t][i]
// Block: 128 threads over i, TT time steps staged in smem.
// ---------------------------------------------------------------------------
#define DRIVE_TT 25
__global__ __launch_bounds__(128) void drive_kernel(
    const float* __restrict__ u, const float* __restrict__ W_in,
    const float* __restrict__ eps)
{
    __shared__ float us[DRIVE_TT][N_IN];
    int i  = blockIdx.x * 128 + threadIdx.x;
    int t0 = blockIdx.y * DRIVE_TT;

    for (int idx = threadIdx.x; idx < DRIVE_TT * N_IN; idx += 128) {
        int tl = idx / N_IN, k = idx % N_IN;
        us[tl][k] = u[(size_t)(t0 + tl) * N_IN + k];
    }
    __syncthreads();
    if (i >= N_REC) return;

    const float* __restrict__ Wr = W_in + (size_t)i * N_IN;
    for (int tl = 0; tl < DRIVE_TT; ++tl) {
        float acc = 0.0f;
        #pragma unroll 4
        for (int k = 0; k < N_IN; ++k)
            acc += __ldg(Wr + k) * us[tl][k];
        int t = t0 + tl;
        g_drive[(size_t)t * N_REC + i] = acc + eps[(size_t)t * N_REC + i];
    }
}

// ---------------------------------------------------------------------------
// One recurrence step: warp-per-row matvec over W_rec (L2-resident, 100 MB).
//   y   = W_rec @ r_prev            (r_prev = hidden[t])
//   x   = 0.9*x + 0.1*(y + drive_t)
//   hidden[t+1] = tanh(x)
// float4 loads: 4 independent FMA chains, LDG.128 for max bytes/instr.
// ---------------------------------------------------------------------------
__global__ __launch_bounds__(256) void step_kernel(
    float* __restrict__ hidden, const float* __restrict__ W, int t)
{
    int gwarp = (blockIdx.x * blockDim.x + threadIdx.x) >> 5;
    int lane  = threadIdx.x & 31;
    if (gwarp >= N_REC) return;

    const float4* __restrict__ Wrow = (const float4*)W + (size_t)gwarp * NR4;
    const float4* __restrict__ r4   = (const float4*)(hidden + (size_t)t * N_REC);

    float4 acc = make_float4(0.f, 0.f, 0.f, 0.f);
    #pragma unroll 4
    for (int v = lane; v < NR4; v += 32) {
        float4 w  = __ldg(Wrow + v);
        float4 rv = __ldg(r4 + v);
        acc.x += w.x * rv.x;
        acc.y += w.y * rv.y;
        acc.z += w.z * rv.z;
        acc.w += w.w * rv.w;
    }
    float s = (acc.x + acc.y) + (acc.z + acc.w);
    #pragma unroll
    for (int o = 16; o; o >>= 1) s += __shfl_xor_sync(0xffffffffu, s, o);

    if (lane == 0) {
        float x = g_x[gwarp];
        x = 0.9f * x + 0.1f * (s + g_drive[(size_t)t * N_REC + gwarp]);
        g_x[gwarp] = x;
        hidden[(size_t)(t + 1) * N_REC + gwarp] = tanhf(x);
    }
}

// ---------------------------------------------------------------------------
// o[t][j] = sum_i hidden[t+1][i] * W_out[j][i]
// Block handles OT consecutive t's; task order keeps W_out row hot in L1.
// ---------------------------------------------------------------------------
#define OUT_OT 4
__global__ __launch_bounds__(256) void out_kernel(
    const float* __restrict__ hidden, const float* __restrict__ W_out,
    float* __restrict__ o)
{
    int w    = threadIdx.x >> 5;
    int lane = threadIdx.x & 31;
    int t0   = blockIdx.x * OUT_OT;

    for (int task = w; task < N_OUT * OUT_OT; task += 8) {
        int j  = task / OUT_OT;
        int tl = task % OUT_OT;
        int t  = t0 + tl;

        const float4* __restrict__ Wr = (const float4*)(W_out + (size_t)j * N_REC);
        const float4* __restrict__ rr = (const float4*)(hidden + (size_t)(t + 1) * N_REC);

        float4 a = make_float4(0.f, 0.f, 0.f, 0.f);
        #pragma unroll 4
        for (int v = lane; v < NR4; v += 32) {
            float4 wv = __ldg(Wr + v);
            float4 rv = __ldg(rr + v);
            a.x += wv.x * rv.x;
            a.y += wv.y * rv.y;
            a.z += wv.z * rv.z;
            a.w += wv.w * rv.w;
        }
        float s = (a.x + a.y) + (a.z + a.w);
        #pragma unroll
        for (int off = 16; off; off >>= 1) s += __shfl_xor_sync(0xffffffffu, s, off);
        if (lane == 0) o[(size_t)t * N_OUT + j] = s;
    }
}

// ---------------------------------------------------------------------------
// kernel_launch: graph-capturable, allocation-free, default-stream ordered.
// Inputs (metadata order = setup_inputs dict order):
//   0: u     [600,100]    1: r    [5000]      2: W_in [5000,100]
//   3: W_rec [5000,5000]  4: W_out[100,5000]  5: eps  [600,5000]
// Output: hidden_states [601,5000] then o [600,100], flattened.
// ---------------------------------------------------------------------------
extern "C" void kernel_launch(void* const* d_in, const int* in_sizes, int n_in,
                              void* d_out, int out_size)
{
    const float* u     = (const float*)d_in[0];
    const float* r     = (const float*)d_in[1];
    const float* W_in  = (const float*)d_in[2];
    const float* W_rec = (const float*)d_in[3];
    const float* W_out = (const float*)d_in[4];
    const float* eps   = (const float*)d_in[5];

    float* hidden = (float*)d_out;                          // [601, 5000]
    float* o      = hidden + (size_t)(T_STEPS + 1) * N_REC; // [600, 100]

    init_kernel<<<(N_REC + 255) / 256, 256>>>(r, hidden);

    dim3 dgrid((N_REC + 127) / 128, T_STEPS / DRIVE_TT);
    drive_kernel<<<dgrid, 128>>>(u, W_in, eps);

    const int step_blocks = (N_REC * 32 + 255) / 256; // warp per row
    for (int t = 0; t < T_STEPS; ++t)
        step_kernel<<<step_blocks, 256>>>(hidden, W_rec, t);

    out_kernel<<<T_STEPS / OUT_OT, 256>>>(hidden, W_out, o);
}

// round 2
// speedup vs baseline: 1.2667x; 1.2667x over previous
#include <cuda_runtime.h>
#include <cuda_bf16.h>
#include <cstddef>

// Problem constants (match reference_code)
#define T_STEPS 600
#define N_REC   5000
#define N_IN    100
#define N_OUT   100
#define NR4     1250   // N_REC / 4

// Scratch (allocation-free rule: __device__ globals)
__device__ float g_x[N_REC];                       // recurrent pre-activation state
__device__ float g_drive[(size_t)T_STEPS * N_REC]; // u @ W_in^T + eps, precomputed

// ---------------------------------------------------------------------------
// init: hidden[0] = r, x = arctanh(r)
// ---------------------------------------------------------------------------
__global__ void init_kernel(const float* __restrict__ r, float* __restrict__ hidden) {
    int i = blockIdx.x * blockDim.x + threadIdx.x;
    if (i < N_REC) {
        float rv = r[i];
        hidden[i] = rv;
        g_x[i] = atanhf(rv);
    }
}

// ---------------------------------------------------------------------------
// drive[t][i] = sum_k u[t][k] * W_in[i][k] + eps[t][i]
// ---------------------------------------------------------------------------
#define DRIVE_TT 25
__global__ __launch_bounds__(128) void drive_kernel(
    const float* __restrict__ u, const float* __restrict__ W_in,
    const float* __restrict__ eps)
{
    __shared__ float us[DRIVE_TT][N_IN];
    int i  = blockIdx.x * 128 + threadIdx.x;
    int t0 = blockIdx.y * DRIVE_TT;

    for (int idx = threadIdx.x; idx < DRIVE_TT * N_IN; idx += 128) {
        int tl = idx / N_IN, k = idx % N_IN;
        us[tl][k] = u[(size_t)(t0 + tl) * N_IN + k];
    }
    __syncthreads();
    if (i >= N_REC) return;

    const float* __restrict__ Wr = W_in + (size_t)i * N_IN;
    for (int tl = 0; tl < DRIVE_TT; ++tl) {
        float acc = 0.0f;
        #pragma unroll 4
        for (int k = 0; k < N_IN; ++k)
            acc += __ldg(Wr + k) * us[tl][k];
        int t = t0 + tl;
        g_drive[(size_t)t * N_REC + i] = acc + eps[(size_t)t * N_REC + i];
    }
}

// ---------------------------------------------------------------------------
// Recurrence step v2.
//   - 512-thread blocks, 8 rows/block, 2 sub-warps per row (10k working warps)
//     -> high LDG MLP (target: LTS/DRAM roofline, not latency-bound).
//   - r_prev staged in shared memory once per block (halves global load count).
//   - Boustrophedon row order across steps (t odd -> reversed block->row map)
//     so the ~104 MB cyclic working set stops thrashing the ~126 MB L2.
// ---------------------------------------------------------------------------
#define STEP_THREADS 512
#define ROWS_PER_BLK 8
#define STEP_BLOCKS  (N_REC / ROWS_PER_BLK)   // 625

__global__ __launch_bounds__(STEP_THREADS, 4) void step_kernel(
    float* __restrict__ hidden, const float* __restrict__ W, int t)
{
    __shared__ float4 rs[NR4];           // 20 KB: r_prev staged
    __shared__ float  part[2 * ROWS_PER_BLK];

    // stage r_prev (hidden[t]) into smem
    const float4* __restrict__ rg = (const float4*)(hidden + (size_t)t * N_REC);
    for (int i = threadIdx.x; i < NR4; i += STEP_THREADS) rs[i] = rg[i];
    __syncthreads();

    // boustrophedon: reverse global streaming order on odd steps
    int rb = (t & 1) ? (STEP_BLOCKS - 1 - (int)blockIdx.x) : (int)blockIdx.x;

    int w    = threadIdx.x >> 5;
    int lane = threadIdx.x & 31;
    int rloc = w >> 1;            // row within block: 0..7
    int sub  = w & 1;             // sub-warp: covers even/odd 32-wide column tiles
    int row  = rb * ROWS_PER_BLK + rloc;

    const float4* __restrict__ Wr = (const float4*)W + (size_t)row * NR4;

    float4 acc = make_float4(0.f, 0.f, 0.f, 0.f);
    int base = lane + (sub << 5); // 0..63
    // 20 iterations cover 64*20=1280 >= 1250; last iter predicated.
    #pragma unroll
    for (int i = 0; i < 20; ++i) {
        int idx = base + (i << 6);
        if (idx < NR4) {
            float4 wv = __ldg(Wr + idx);
            float4 rv = rs[idx];
            acc.x += wv.x * rv.x;
            acc.y += wv.y * rv.y;
            acc.z += wv.z * rv.z;
            acc.w += wv.w * rv.w;
        }
    }
    float s = (acc.x + acc.y) + (acc.z + acc.w);
    #pragma unroll
    for (int o = 16; o; o >>= 1) s += __shfl_xor_sync(0xffffffffu, s, o);
    if (lane == 0) part[w] = s;
    __syncthreads();

    // one thread per row finishes the state update
    if (threadIdx.x < ROWS_PER_BLK) {
        int r2 = rb * ROWS_PER_BLK + threadIdx.x;
        float y = part[2 * threadIdx.x] + part[2 * threadIdx.x + 1];
        float x = g_x[r2];
        x = 0.9f * x + 0.1f * (y + g_drive[(size_t)t * N_REC + r2]);
        g_x[r2] = x;
        hidden[(size_t)(t + 1) * N_REC + r2] = tanhf(x);
    }
}

// ---------------------------------------------------------------------------
// o[t][j] = sum_i hidden[t+1][i] * W_out[j][i]
// ---------------------------------------------------------------------------
#define OUT_OT 4
__global__ __launch_bounds__(256) void out_kernel(
    const float* __restrict__ hidden, const float* __restrict__ W_out,
    float* __restrict__ o)
{
    int w    = threadIdx.x >> 5;
    int lane = threadIdx.x & 31;
    int t0   = blockIdx.x * OUT_OT;

    for (int task = w; task < N_OUT * OUT_OT; task += 8) {
        int j  = task / OUT_OT;
        int tl = task % OUT_OT;
        int t  = t0 + tl;

        const float4* __restrict__ Wr = (const float4*)(W_out + (size_t)j * N_REC);
        const float4* __restrict__ rr = (const float4*)(hidden + (size_t)(t + 1) * N_REC);

        float4 a = make_float4(0.f, 0.f, 0.f, 0.f);
        #pragma unroll 4
        for (int v = lane; v < NR4; v += 32) {
            float4 wv = __ldg(Wr + v);
            float4 rv = __ldg(rr + v);
            a.x += wv.x * rv.x;
            a.y += wv.y * rv.y;
            a.z += wv.z * rv.z;
            a.w += wv.w * rv.w;
        }
        float s = (a.x + a.y) + (a.z + a.w);
        #pragma unroll
        for (int off = 16; off; off >>= 1) s += __shfl_xor_sync(0xffffffffu, s, off);
        if (lane == 0) o[(size_t)t * N_OUT + j] = s;
    }
}

// ---------------------------------------------------------------------------
// kernel_launch (graph-capturable, allocation-free)
// Inputs: 0:u [600,100] 1:r [5000] 2:W_in [5000,100] 3:W_rec [5000,5000]
//         4:W_out [100,5000] 5:eps [600,5000]
// Output: hidden_states [601,5000] then o [600,100]
// ---------------------------------------------------------------------------
extern "C" void kernel_launch(void* const* d_in, const int* in_sizes, int n_in,
                              void* d_out, int out_size)
{
    const float* u     = (const float*)d_in[0];
    const float* r     = (const float*)d_in[1];
    const float* W_in  = (const float*)d_in[2];
    const float* W_rec = (const float*)d_in[3];
    const float* W_out = (const float*)d_in[4];
    const float* eps   = (const float*)d_in[5];

    float* hidden = (float*)d_out;                          // [601, 5000]
    float* o      = hidden + (size_t)(T_STEPS + 1) * N_REC; // [600, 100]

    init_kernel<<<(N_REC + 255) / 256, 256>>>(r, hidden);

    dim3 dgrid((N_REC + 127) / 128, T_STEPS / DRIVE_TT);
    drive_kernel<<<dgrid, 128>>>(u, W_in, eps);

    for (int t = 0; t < T_STEPS; ++t)
        step_kernel<<<STEP_BLOCKS, STEP_THREADS>>>(hidden, W_rec, t);

    out_kernel<<<T_STEPS / OUT_OT, 256>>>(hidden, W_out, o);
}

// round 4
// speedup vs baseline: 1.3142x; 1.0375x over previous
#include <cuda_runtime.h>
#include <cuda_bf16.h>
#include <cstddef>

// Problem constants (match reference_code)
#define T_STEPS 600
#define N_REC   5000
#define N_IN    100
#define N_OUT   100
#define NR4     1250   // N_REC / 4  (float4 units)
#define NR8     625    // N_REC / 8  (float8 units; W row = 20000 B = 625*32 B)

// Scratch (allocation-free rule: __device__ globals)
__device__ float g_x[N_REC];                       // recurrent pre-activation state
__device__ float g_drive[(size_t)T_STEPS * N_REC]; // u @ W_in^T + eps, precomputed

// 256-bit L2-persisting load (sm_100a: evict_last requires .v8.b32/.v4.b64).
// Marks W_rec lines sticky in L2 so the 100 MB matrix survives across steps.
__device__ __forceinline__ void ldg_el8(const float* p, float4& a, float4& b) {
    unsigned r0, r1, r2, r3, r4, r5, r6, r7;
    asm("ld.global.nc.L2::evict_last.v8.b32 {%0,%1,%2,%3,%4,%5,%6,%7}, [%8];"
        : "=r"(r0), "=r"(r1), "=r"(r2), "=r"(r3),
          "=r"(r4), "=r"(r5), "=r"(r6), "=r"(r7)
        : "l"(p));
    a.x = __uint_as_float(r0); a.y = __uint_as_float(r1);
    a.z = __uint_as_float(r2); a.w = __uint_as_float(r3);
    b.x = __uint_as_float(r4); b.y = __uint_as_float(r5);
    b.z = __uint_as_float(r6); b.w = __uint_as_float(r7);
}

// ---------------------------------------------------------------------------
// init: hidden[0] = r, x = arctanh(r)
// ---------------------------------------------------------------------------
__global__ void init_kernel(const float* __restrict__ r, float* __restrict__ hidden) {
    int i = blockIdx.x * blockDim.x + threadIdx.x;
    if (i < N_REC) {
        float rv = r[i];
        hidden[i] = rv;
        g_x[i] = atanhf(rv);
    }
}

// ---------------------------------------------------------------------------
// drive[t][i] = sum_k u[t][k] * W_in[i][k] + eps[t][i]
// ---------------------------------------------------------------------------
#define DRIVE_TT 25
__global__ __launch_bounds__(128) void drive_kernel(
    const float* __restrict__ u, const float* __restrict__ W_in,
    const float* __restrict__ eps)
{
    __shared__ float us[DRIVE_TT][N_IN];
    int i  = blockIdx.x * 128 + threadIdx.x;
    int t0 = blockIdx.y * DRIVE_TT;

    for (int idx = threadIdx.x; idx < DRIVE_TT * N_IN; idx += 128) {
        int tl = idx / N_IN, k = idx % N_IN;
        us[tl][k] = u[(size_t)(t0 + tl) * N_IN + k];
    }
    __syncthreads();
    if (i >= N_REC) return;

    const float* __restrict__ Wr = W_in + (size_t)i * N_IN;
    for (int tl = 0; tl < DRIVE_TT; ++tl) {
        float acc = 0.0f;
        #pragma unroll 4
        for (int k = 0; k < N_IN; ++k)
            acc += __ldg(Wr + k) * us[tl][k];
        int t = t0 + tl;
        g_drive[(size_t)t * N_REC + i] = acc + eps[(size_t)t * N_REC + i];
    }
}

// ---------------------------------------------------------------------------
// Recurrence step v4.
//   - W via 256-bit ld.global.nc.L2::evict_last -> W_rec stays L2-resident.
//   - launch_bounds(512,2): 64-reg budget, loads front-batched (MLP up).
//   - 64 lanes per row sweep 625 float8 units: 9 full iters + 49-lane tail.
//   - r_prev staged in smem; boustrophedon order retained.
// ---------------------------------------------------------------------------
#define STEP_THREADS 512
#define ROWS_PER_BLK 8
#define STEP_BLOCKS  (N_REC / ROWS_PER_BLK)   // 625

__global__ __launch_bounds__(STEP_THREADS, 2) void step_kernel(
    float* __restrict__ hidden, const float* __restrict__ W, int t)
{
    __shared__ float4 rs[NR4];           // 20 KB: r_prev staged
    __shared__ float  part[2 * ROWS_PER_BLK];

    const float4* __restrict__ rg = (const float4*)(hidden + (size_t)t * N_REC);
    for (int i = threadIdx.x; i < NR4; i += STEP_THREADS) rs[i] = rg[i];
    __syncthreads();

    int rb = (t & 1) ? (STEP_BLOCKS - 1 - (int)blockIdx.x) : (int)blockIdx.x;

    int w    = threadIdx.x >> 5;
    int lane = threadIdx.x & 31;
    int rloc = w >> 1;            // row within block: 0..7
    int sub  = w & 1;             // sub-warp: even/odd 32-wide float8 tiles
    int row  = rb * ROWS_PER_BLK + rloc;

    const float* __restrict__ Wr = W + (size_t)row * N_REC;

    int base = lane + (sub << 5); // 0..63, in float8 units
    float4 a0 = make_float4(0.f, 0.f, 0.f, 0.f);
    float4 a1 = make_float4(0.f, 0.f, 0.f, 0.f);

    // 9 full iterations cover float8 idx 0..575 (unpredicated -> batched LDGs)
    #pragma unroll
    for (int i = 0; i < 9; ++i) {
        int idx = base + (i << 6);
        float4 wa, wb;
        ldg_el8(Wr + idx * 8, wa, wb);
        float4 ra = rs[2 * idx], rb4 = rs[2 * idx + 1];
        a0.x += wa.x * ra.x;  a0.y += wa.y * ra.y;
        a0.z += wa.z * ra.z;  a0.w += wa.w * ra.w;
        a1.x += wb.x * rb4.x; a1.y += wb.y * rb4.y;
        a1.z += wb.z * rb4.z; a1.w += wb.w * rb4.w;
    }
    // tail: idx 576..624 (49 of 64 lanes)
    {
        int idx = base + (9 << 6);
        if (idx < NR8) {
            float4 wa, wb;
            ldg_el8(Wr + idx * 8, wa, wb);
            float4 ra = rs[2 * idx], rb4 = rs[2 * idx + 1];
            a0.x += wa.x * ra.x;  a0.y += wa.y * ra.y;
            a0.z += wa.z * ra.z;  a0.w += wa.w * ra.w;
            a1.x += wb.x * rb4.x; a1.y += wb.y * rb4.y;
            a1.z += wb.z * rb4.z; a1.w += wb.w * rb4.w;
        }
    }

    float s = ((a0.x + a1.x) + (a0.y + a1.y)) + ((a0.z + a1.z) + (a0.w + a1.w));
    #pragma unroll
    for (int o = 16; o; o >>= 1) s += __shfl_xor_sync(0xffffffffu, s, o);
    if (lane == 0) part[w] = s;
    __syncthreads();

    if (threadIdx.x < ROWS_PER_BLK) {
        int r2 = rb * ROWS_PER_BLK + threadIdx.x;
        float y = part[2 * threadIdx.x] + part[2 * threadIdx.x + 1];
        float x = g_x[r2];
        x = 0.9f * x + 0.1f * (y + g_drive[(size_t)t * N_REC + r2]);
        g_x[r2] = x;
        hidden[(size_t)(t + 1) * N_REC + r2] = tanhf(x);
    }
}

// ---------------------------------------------------------------------------
// o[t][j] = sum_i hidden[t+1][i] * W_out[j][i]
// ---------------------------------------------------------------------------
#define OUT_OT 4
__global__ __launch_bounds__(256) void out_kernel(
    const float* __restrict__ hidden, const float* __restrict__ W_out,
    float* __restrict__ o)
{
    int w    = threadIdx.x >> 5;
    int lane = threadIdx.x & 31;
    int t0   = blockIdx.x * OUT_OT;

    for (int task = w; task < N_OUT * OUT_OT; task += 8) {
        int j  = task / OUT_OT;
        int tl = task % OUT_OT;
        int t  = t0 + tl;

        const float4* __restrict__ Wr = (const float4*)(W_out + (size_t)j * N_REC);
        const float4* __restrict__ rr = (const float4*)(hidden + (size_t)(t + 1) * N_REC);

        float4 a = make_float4(0.f, 0.f, 0.f, 0.f);
        #pragma unroll 4
        for (int v = lane; v < NR4; v += 32) {
            float4 wv = __ldg(Wr + v);
            float4 rv = __ldg(rr + v);
            a.x += wv.x * rv.x;
            a.y += wv.y * rv.y;
            a.z += wv.z * rv.z;
            a.w += wv.w * rv.w;
        }
        float s = (a.x + a.y) + (a.z + a.w);
        #pragma unroll
        for (int off = 16; off; off >>= 1) s += __shfl_xor_sync(0xffffffffu, s, off);
        if (lane == 0) o[(size_t)t * N_OUT + j] = s;
    }
}

// ---------------------------------------------------------------------------
// kernel_launch (graph-capturable, allocation-free)
// Inputs: 0:u [600,100] 1:r [5000] 2:W_in [5000,100] 3:W_rec [5000,5000]
//         4:W_out [100,5000] 5:eps [600,5000]
// Output: hidden_states [601,5000] then o [600,100]
// ---------------------------------------------------------------------------
extern "C" void kernel_launch(void* const* d_in, const int* in_sizes, int n_in,
                              void* d_out, int out_size)
{
    const float* u     = (const float*)d_in[0];
    const float* r     = (const float*)d_in[1];
    const float* W_in  = (const float*)d_in[2];
    const float* W_rec = (const float*)d_in[3];
    const float* W_out = (const float*)d_in[4];
    const float* eps   = (const float*)d_in[5];

    float* hidden = (float*)d_out;                          // [601, 5000]
    float* o      = hidden + (size_t)(T_STEPS + 1) * N_REC; // [600, 100]

    init_kernel<<<(N_REC + 255) / 256, 256>>>(r, hidden);

    dim3 dgrid((N_REC + 127) / 128, T_STEPS / DRIVE_TT);
    drive_kernel<<<dgrid, 128>>>(u, W_in, eps);

    for (int t = 0; t < T_STEPS; ++t)
        step_kernel<<<STEP_BLOCKS, STEP_THREADS>>>(hidden, W_rec, t);

    out_kernel<<<T_STEPS / OUT_OT, 256>>>(hidden, W_out, o);
}

// round 6
// speedup vs baseline: 1.6410x; 1.2487x over previous
#include <cuda_runtime.h>
#include <cuda_bf16.h>
#include <cstddef>

// Problem constants (match reference_code)
#define T_STEPS 600
#define N_REC   5000
#define N_IN    100
#define N_OUT   100
#define NR4     1250   // N_REC / 4  (float4 units)
#define NR8     625    // N_REC / 8  (float8 units)

#define WARPS    24
#define PTHREADS (WARPS * 32)   // 768
#define P_PIN    10             // W rows pinned in SMEM per block (200 KB)

// Scratch (allocation-free rule: __device__ globals)
__device__ float    g_x[N_REC];
__device__ float    g_drive[(size_t)T_STEPS * N_REC];
__device__ unsigned g_bar;      // grid barrier counter (reset each launch)

// 256-bit L2-persisting load (sm_100a: evict_last requires .v8.b32)
__device__ __forceinline__ void ldg_el8(const float* p, float4& a, float4& b) {
    unsigned r0, r1, r2, r3, r4, r5, r6, r7;
    asm("ld.global.nc.L2::evict_last.v8.b32 {%0,%1,%2,%3,%4,%5,%6,%7}, [%8];"
        : "=r"(r0), "=r"(r1), "=r"(r2), "=r"(r3),
          "=r"(r4), "=r"(r5), "=r"(r6), "=r"(r7)
        : "l"(p));
    a.x = __uint_as_float(r0); a.y = __uint_as_float(r1);
    a.z = __uint_as_float(r2); a.w = __uint_as_float(r3);
    b.x = __uint_as_float(r4); b.y = __uint_as_float(r5);
    b.z = __uint_as_float(r6); b.w = __uint_as_float(r7);
}

__device__ __forceinline__ unsigned ld_acq(const unsigned* p) {
    unsigned v;
    asm volatile("ld.global.acquire.gpu.u32 %0, [%1];" : "=r"(v) : "l"(p));
    return v;
}

// ---------------------------------------------------------------------------
// init: hidden[0] = r, x = arctanh(r), reset grid barrier
// ---------------------------------------------------------------------------
__global__ void init_kernel(const float* __restrict__ r, float* __restrict__ hidden) {
    int i = blockIdx.x * blockDim.x + threadIdx.x;
    if (i == 0) g_bar = 0u;
    if (i < N_REC) {
        float rv = r[i];
        hidden[i] = rv;
        g_x[i] = atanhf(rv);
    }
}

// ---------------------------------------------------------------------------
// drive[t][i] = sum_k u[t][k] * W_in[i][k] + eps[t][i]
// ---------------------------------------------------------------------------
#define DRIVE_TT 25
__global__ __launch_bounds__(128) void drive_kernel(
    const float* __restrict__ u, const float* __restrict__ W_in,
    const float* __restrict__ eps)
{
    __shared__ float us[DRIVE_TT][N_IN];
    int i  = blockIdx.x * 128 + threadIdx.x;
    int t0 = blockIdx.y * DRIVE_TT;

    for (int idx = threadIdx.x; idx < DRIVE_TT * N_IN; idx += 128) {
        int tl = idx / N_IN, k = idx % N_IN;
        us[tl][k] = u[(size_t)(t0 + tl) * N_IN + k];
    }
    __syncthreads();
    if (i >= N_REC) return;

    const float* __restrict__ Wr = W_in + (size_t)i * N_IN;
    for (int tl = 0; tl < DRIVE_TT; ++tl) {
        float acc = 0.0f;
        #pragma unroll 4
        for (int k = 0; k < N_IN; ++k)
            acc += __ldg(Wr + k) * us[tl][k];
        int t = t0 + tl;
        g_drive[(size_t)t * N_REC + i] = acc + eps[(size_t)t * N_REC + i];
    }
}

// ---------------------------------------------------------------------------
// warp dot products (result valid on all lanes)
// ---------------------------------------------------------------------------
__device__ __forceinline__ float warp_reduce(float s) {
    #pragma unroll
    for (int o = 16; o; o >>= 1) s += __shfl_xor_sync(0xffffffffu, s, o);
    return s;
}

// streamed row: W from global (float8 evict_last), r from smem
__device__ __forceinline__ float dot_stream(const float* __restrict__ Wr,
                                            const float4* __restrict__ rs, int lane) {
    float4 a0 = make_float4(0.f,0.f,0.f,0.f), a1 = make_float4(0.f,0.f,0.f,0.f);
    #pragma unroll
    for (int i = 0; i < 19; ++i) {           // float8 idx 0..607
        int idx = lane + (i << 5);
        float4 wa, wb;
        ldg_el8(Wr + (size_t)idx * 8, wa, wb);
        float4 ra = rs[2*idx], rb = rs[2*idx+1];
        a0.x += wa.x*ra.x; a0.y += wa.y*ra.y; a0.z += wa.z*ra.z; a0.w += wa.w*ra.w;
        a1.x += wb.x*rb.x; a1.y += wb.y*rb.y; a1.z += wb.z*rb.z; a1.w += wb.w*rb.w;
    }
    int idx = lane + (19 << 5);              // 608..624 -> lanes 0..16
    if (idx < NR8) {
        float4 wa, wb;
        ldg_el8(Wr + (size_t)idx * 8, wa, wb);
        float4 ra = rs[2*idx], rb = rs[2*idx+1];
        a0.x += wa.x*ra.x; a0.y += wa.y*ra.y; a0.z += wa.z*ra.z; a0.w += wa.w*ra.w;
        a1.x += wb.x*rb.x; a1.y += wb.y*rb.y; a1.z += wb.z*rb.z; a1.w += wb.w*rb.w;
    }
    float s = ((a0.x+a1.x)+(a0.y+a1.y)) + ((a0.z+a1.z)+(a0.w+a1.w));
    return warp_reduce(s);
}

// pinned row: W from smem, r from smem
__device__ __forceinline__ float dot_pin(const float4* __restrict__ Wp,
                                         const float4* __restrict__ rs, int lane) {
    float4 a0 = make_float4(0.f,0.f,0.f,0.f), a1 = make_float4(0.f,0.f,0.f,0.f);
    #pragma unroll 13
    for (int i = 0; i < 39; ++i) {           // float4 idx 0..1247
        int idx = lane + (i << 5);
        float4 w = Wp[idx], rv = rs[idx];
        if (i & 1) { a1.x += w.x*rv.x; a1.y += w.y*rv.y; a1.z += w.z*rv.z; a1.w += w.w*rv.w; }
        else       { a0.x += w.x*rv.x; a0.y += w.y*rv.y; a0.z += w.z*rv.z; a0.w += w.w*rv.w; }
    }
    int idx = lane + (39 << 5);              // 1248..1249 -> lanes 0,1
    if (idx < NR4) {
        float4 w = Wp[idx], rv = rs[idx];
        a0.x += w.x*rv.x; a0.y += w.y*rv.y; a0.z += w.z*rv.z; a0.w += w.w*rv.w;
    }
    float s = ((a0.x+a1.x)+(a0.y+a1.y)) + ((a0.z+a1.z)+(a0.w+a1.w));
    return warp_reduce(s);
}

// ---------------------------------------------------------------------------
// Persistent RNN rollout: one block per SM, all 600 steps in one kernel.
//   - P_PIN rows of W pinned in SMEM per block (never refetched).
//   - remaining rows streamed (evict_last; 70 MB fits L2).
//   - 220 KB dynamic smem -> occupancy 1, grid == #SMs -> single wave,
//     so the atomic-counter grid barrier cannot deadlock.
// ---------------------------------------------------------------------------
__global__ __launch_bounds__(PTHREADS, 1) void rnn_persistent(
    float* __restrict__ hidden, const float* __restrict__ W,
    int G, int pin_total, int n_stream)
{
    extern __shared__ float sm[];
    float4* rs   = (float4*)sm;         // [NR4]  r_prev staging (20000 B)
    float*  Wpin = sm + N_REC;          // P_PIN rows x N_REC floats (200000 B)

    const int b    = blockIdx.x;
    const int tid  = threadIdx.x;
    const int warp = tid >> 5;
    const int lane = tid & 31;

    // one-time copy of this block's pinned rows into SMEM
    {
        const float4* src = (const float4*)(W + (size_t)b * P_PIN * N_REC);
        float4* dst = (float4*)Wpin;
        for (int i = tid; i < P_PIN * NR4; i += PTHREADS) dst[i] = src[i];
    }

    // rows owned by this block: P_PIN pinned + its share of the streamed rows
    const int nrows = P_PIN + (n_stream - b + G - 1) / G;

    for (int t = 0; t < T_STEPS; ++t) {
        // stage r_prev = hidden[t]
        const float4* rg = (const float4*)(hidden + (size_t)t * N_REC);
        for (int i = tid; i < NR4; i += PTHREADS) rs[i] = rg[i];
        __syncthreads();

        // iterate locals high->low: dual-row warps issue their streamed
        // (global, long-latency) row before their pinned (smem) row
        if (warp < nrows) {
            int local = warp + WARPS * ((nrows - 1 - warp) / WARPS);
            for (; local >= 0; local -= WARPS) {
                int   row;
                float s;
                if (local < P_PIN) {
                    row = b * P_PIN + local;
                    s = dot_pin((const float4*)(Wpin + (size_t)local * N_REC), rs, lane);
                } else {
                    int sidx = b + (local - P_PIN) * G;
                    row = pin_total + sidx;
                    s = dot_stream(W + (size_t)row * N_REC, rs, lane);
                }
                float x = g_x[row];                       // broadcast load
                x = 0.9f * x + 0.1f * (s + g_drive[(size_t)t * N_REC + row]);
                if (lane == 0) {
                    g_x[row] = x;
                    hidden[(size_t)(t + 1) * N_REC + row] = tanhf(x);
                }
            }
        }
        __syncthreads();

        // grid barrier: publish writes, arrive, spin (with nanosleep) until
        // all G blocks have arrived for this step
        if (tid == 0) {
            __threadfence();
            atomicAdd(&g_bar, 1u);
            unsigned tgt = (unsigned)G * (unsigned)(t + 1);
            while (ld_acq(&g_bar) < tgt) __nanosleep(64);
        }
        __syncthreads();
    }
}

// ---------------------------------------------------------------------------
// o[t][j] = sum_i hidden[t+1][i] * W_out[j][i]
// ---------------------------------------------------------------------------
#define OUT_OT 4
__global__ __launch_bounds__(256) void out_kernel(
    const float* __restrict__ hidden, const float* __restrict__ W_out,
    float* __restrict__ o)
{
    int w    = threadIdx.x >> 5;
    int lane = threadIdx.x & 31;
    int t0   = blockIdx.x * OUT_OT;

    for (int task = w; task < N_OUT * OUT_OT; task += 8) {
        int j  = task / OUT_OT;
        int tl = task % OUT_OT;
        int t  = t0 + tl;

        const float4* __restrict__ Wr = (const float4*)(W_out + (size_t)j * N_REC);
        const float4* __restrict__ rr = (const float4*)(hidden + (size_t)(t + 1) * N_REC);

        float4 a = make_float4(0.f, 0.f, 0.f, 0.f);
        #pragma unroll 4
        for (int v = lane; v < NR4; v += 32) {
            float4 wv = __ldg(Wr + v);
            float4 rv = __ldg(rr + v);
            a.x += wv.x * rv.x;
            a.y += wv.y * rv.y;
            a.z += wv.z * rv.z;
            a.w += wv.w * rv.w;
        }
        float s = warp_reduce((a.x + a.y) + (a.z + a.w));
        if (lane == 0) o[(size_t)t * N_OUT + j] = s;
    }
}

// ---------------------------------------------------------------------------
// kernel_launch (graph-capturable, allocation-free)
// Inputs: 0:u [600,100] 1:r [5000] 2:W_in [5000,100] 3:W_rec [5000,5000]
//         4:W_out [100,5000] 5:eps [600,5000]
// Output: hidden_states [601,5000] then o [600,100]
// ---------------------------------------------------------------------------
extern "C" void kernel_launch(void* const* d_in, const int* in_sizes, int n_in,
                              void* d_out, int out_size)
{
    const float* u     = (const float*)d_in[0];
    const float* r     = (const float*)d_in[1];
    const float* W_in  = (const float*)d_in[2];
    const float* W_rec = (const float*)d_in[3];
    const float* W_out = (const float*)d_in[4];
    const float* eps   = (const float*)d_in[5];

    float* hidden = (float*)d_out;                          // [601, 5000]
    float* o      = hidden + (size_t)(T_STEPS + 1) * N_REC; // [600, 100]

    int dev = 0, sms = 148;
    cudaGetDevice(&dev);
    cudaDeviceGetAttribute(&sms, cudaDevAttrMultiProcessorCount, dev);
    int G = sms;
    if (G < 1) G = 1;
    if (G * P_PIN > N_REC) G = N_REC / P_PIN;               // safety clamp
    const int pin_total = G * P_PIN;
    const int n_stream  = N_REC - pin_total;

    const size_t shbytes = (size_t)(N_REC + P_PIN * N_REC) * sizeof(float); // 220000
    cudaFuncSetAttribute(rnn_persistent,
                         cudaFuncAttributeMaxDynamicSharedMemorySize, (int)shbytes);

    init_kernel<<<(N_REC + 255) / 256, 256>>>(r, hidden);

    dim3 dgrid((N_REC + 127) / 128, T_STEPS / DRIVE_TT);
    drive_kernel<<<dgrid, 128>>>(u, W_in, eps);

    rnn_persistent<<<G, PTHREADS, shbytes>>>(hidden, W_rec, G, pin_total, n_stream);

    out_kernel<<<T_STEPS / OUT_OT, 256>>>(hidden, W_out, o);
}